// round 8
// baseline (speedup 1.0000x reference)
#include <cuda_runtime.h>
#include <cstdint>

// TransferNet: B=8192 sequences, T=1024 steps, C=6 channels.
// s_j(t) = a*feats[b,t,j] + (1-a)*ln( sum_i exp( s_i(t-1)*Tn[i][j] ) )
// s(0) = feats[b,0,:], out[b,t,:] = s(t).
//
// R5 skeleton (best: 119us): 6 lanes/batch, 5 groups/warp, 4 warps/block ->
// 20 batches/block; in-place smem tile; NCHUNK=4 T-chunks with W=12 warmup
// (contraction, seed error ~5e-9).
// R8 deltas:
//  (1) per-block phase stagger: first tile 16/32/48/64 steps so co-resident
//      blocks' copy phases interleave with others' compute (MUFU stays fed),
//  (2) fused store(k)+load(k+1) phase: same thread-owned slots, LDS->STG
//      then LDG->STS per slot; 2 barriers/tile instead of 3, earlier LDGs.

constexpr int T_STEPS  = 1024;
constexpr int C        = 6;
constexpr int BPB      = 20;            // 4 warps * 5 groups
constexpr int NTHREADS = 128;
constexpr int TT       = 64;            // max tile steps (smem sized for this)
constexpr int CT       = 256;           // steps per chunk
constexpr int NCHUNK   = T_STEPS / CT;  // 4
constexpr int W        = 12;            // warmup steps (incl. seed)
constexpr int ROW      = T_STEPS * C;   // 6144
constexpr int S_STRIDE = 134;           // 134 % 32 == 6 -> conflict-free
constexpr float LOG2E_F = 1.4426950408889634f;
constexpr float LN2_F   = 0.6931471805599453f;

__device__ __forceinline__ float ex2f(float x) {
    float r; asm("ex2.approx.ftz.f32 %0, %1;" : "=f"(r) : "f"(x)); return r;
}
__device__ __forceinline__ float lg2f(float x) {
    float r; asm("lg2.approx.ftz.f32 %0, %1;" : "=f"(r) : "f"(x)); return r;
}

// s <- a*cur + c2*lg2( sum_i exp2( s_i * t2[i] ) ), c2 = (1-a)*ln2
__device__ __forceinline__ float step6(float s, float cur, const float* t2,
                                       int gbase, float a, float c2) {
    const unsigned FULL = 0xffffffffu;
    float v0 = __shfl_sync(FULL, s, gbase + 0);
    float v1 = __shfl_sync(FULL, s, gbase + 1);
    float v2 = __shfl_sync(FULL, s, gbase + 2);
    float v3 = __shfl_sync(FULL, s, gbase + 3);
    float v4 = __shfl_sync(FULL, s, gbase + 4);
    float v5 = __shfl_sync(FULL, s, gbase + 5);
    float e0 = ex2f(v0 * t2[0]);
    float e1 = ex2f(v1 * t2[1]);
    float e2 = ex2f(v2 * t2[2]);
    float e3 = ex2f(v3 * t2[3]);
    float e4 = ex2f(v4 * t2[4]);
    float e5 = ex2f(v5 * t2[5]);
    float acc = ((e0 + e1) + (e2 + e3)) + (e4 + e5);
    return fmaf(a, cur, c2 * lg2f(acc));
}

__global__ __launch_bounds__(NTHREADS, 6)
void transfer_kernel(const float* __restrict__ feats,
                     const float* __restrict__ alpha,
                     const float* __restrict__ trans,
                     float* __restrict__ out, int B)
{
    __shared__ float tile[TT * S_STRIDE];

    const int tid  = threadIdx.x;
    const int warp = tid >> 5;
    const int lane = tid & 31;
    int g = lane / 6; if (g > 4) g = 4;       // lanes 30,31: dummies
    const int j     = lane - (lane / 6) * 6;
    const int gbase = g * 6;
    const int coff  = warp * 32 + lane;

    const int b0 = blockIdx.x * BPB;
    const int t0 = blockIdx.y * CT;
    int nvalid = B - b0; if (nvalid > BPB) nvalid = BPB;

    // a = sigmoid(alpha)
    const float av = alpha[0];
    const float a  = 1.0f / (1.0f + __expf(-av));
    const float c2 = (1.0f - a) * LN2_F;

    // Row-softmax of transitions; column j, pre-scaled by log2(e)
    float t2[6];
    #pragma unroll
    for (int i = 0; i < 6; ++i) {
        float row[6], m = -1e30f;
        #pragma unroll
        for (int k = 0; k < 6; ++k) { row[k] = trans[i * 6 + k]; m = fmaxf(m, row[k]); }
        float sum = 0.f, ej = 0.f;
        #pragma unroll
        for (int k = 0; k < 6; ++k) {
            float e = ex2f((row[k] - m) * LOG2E_F);
            sum += e;
            if (k == j) ej = e;
        }
        t2[i] = (ej / sum) * LOG2E_F;
    }

    // Per-thread copy offsets (constant).
    const int r0 = tid, r1 = tid + 128, r2 = tid + 256;
    const int s0 = (r0 / 6) * S_STRIDE + (r0 % 6);
    const int s1 = (r1 / 6) * S_STRIDE + (r1 % 6);
    const int s2 = (r2 / 6) * S_STRIDE + (r2 % 6);

    float s = 0.f;

    // ---- warmup (chunks > 0): seed s = feats[t0-W], 11 unstored steps ----
    if (blockIdx.y > 0) {
        int bb = b0 + warp * 5 + g; if (bb >= B) bb = B - 1;
        const float* fp = feats + (size_t)bb * ROW + (size_t)(t0 - W) * C + j;
        float cw[6];
        #pragma unroll
        for (int w = 0; w < 6; ++w) cw[w] = fp[w * C];
        s = cw[0];
        #pragma unroll
        for (int w = 1; w < 6; ++w) s = step6(s, cw[w], t2, gbase, a, c2);
        #pragma unroll
        for (int w = 0; w < 6; ++w) cw[w] = fp[(6 + w) * C];
        #pragma unroll
        for (int w = 0; w < 6; ++w) s = step6(s, cw[w], t2, gbase, a, c2);
    }

    const float* fbase = feats + (size_t)b0 * ROW + (size_t)t0 * C;
    float*       obase = out   + (size_t)b0 * ROW + (size_t)t0 * C;

    // ---- stagger: first tile 64/48/32/16 steps by block parity ----
    const int f = TT - ((blockIdx.x + blockIdx.y) & 3) * 16;

    // initial load: tile [0, f)
    {
        const int lim = f * C;
        #pragma unroll
        for (int bl = 0; bl < BPB; ++bl) {
            const int sb = (bl / 5) * 32 + (bl % 5) * 6;   // compile-time
            if (bl < nvalid) {
                const float* gp = fbase + (size_t)bl * ROW;
                if (r0 < lim) tile[s0 + sb] = gp[r0];
                if (r1 < lim) tile[s1 + sb] = gp[r1];
                if (r2 < lim) tile[s2 + sb] = gp[r2];
            }
        }
    }
    __syncthreads();

    int tc = 0, len = f;
    while (true) {
        // ---- compute current tile in place ----
        int tstart = 0;
        if (blockIdx.y == 0 && tc == 0) { s = tile[coff]; tstart = 1; }

        #pragma unroll 4
        for (int tt = tstart; tt < len; ++tt) {
            float cur = tile[tt * S_STRIDE + coff];
            s = step6(s, cur, t2, gbase, a, c2);
            tile[tt * S_STRIDE + coff] = s;
        }
        __syncthreads();

        const int next = tc + len;
        float* gdst = obase + (size_t)tc * C;
        const int lim_s = len * C;

        if (next >= CT) {
            // ---- final: store only ----
            #pragma unroll
            for (int bl = 0; bl < BPB; ++bl) {
                const int sb = (bl / 5) * 32 + (bl % 5) * 6;
                if (bl < nvalid) {
                    float* gp = gdst + (size_t)bl * ROW;
                    if (r0 < lim_s) gp[r0] = tile[s0 + sb];
                    if (r1 < lim_s) gp[r1] = tile[s1 + sb];
                    if (r2 < lim_s) gp[r2] = tile[s2 + sb];
                }
            }
            break;
        }

        // ---- fused: store tile [tc,tc+len) + load tile [next,next+nlen) ----
        int nlen = CT - next; if (nlen > TT) nlen = TT;
        const int lim_l = nlen * C;
        const float* gsrc = fbase + (size_t)next * C;

        #pragma unroll
        for (int bl = 0; bl < BPB; ++bl) {
            const int sb = (bl / 5) * 32 + (bl % 5) * 6;
            if (bl < nvalid) {
                float* gp = gdst + (size_t)bl * ROW;
                const float* gl = gsrc + (size_t)bl * ROW;
                // store (LDS->STG), then reload same slots (LDG->STS):
                // identical smem addresses per thread => no hazard.
                if (r0 < lim_s) gp[r0] = tile[s0 + sb];
                if (r1 < lim_s) gp[r1] = tile[s1 + sb];
                if (r2 < lim_s) gp[r2] = tile[s2 + sb];
                if (r0 < lim_l) tile[s0 + sb] = gl[r0];
                if (r1 < lim_l) tile[s1 + sb] = gl[r1];
                if (r2 < lim_l) tile[s2 + sb] = gl[r2];
            }
        }
        __syncthreads();

        tc = next; len = nlen;
    }
}

extern "C" void kernel_launch(void* const* d_in, const int* in_sizes, int n_in,
                              void* d_out, int out_size) {
    const float* feats = (const float*)d_in[0];
    const float* alpha = (const float*)d_in[1];
    const float* trans = (const float*)d_in[2];
    float* out = (float*)d_out;
    (void)n_in; (void)out_size;

    int B = in_sizes[0] / (T_STEPS * C);
    dim3 grid((B + BPB - 1) / BPB, NCHUNK);
    transfer_kernel<<<grid, NTHREADS>>>(feats, alpha, trans, out, B);
}

// round 9
// speedup vs baseline: 1.5479x; 1.5479x over previous
#include <cuda_runtime.h>
#include <cstdint>

// TransferNet: B=8192 sequences, T=1024 steps, C=6 channels.
// s_j(t) = a*feats[b,t,j] + (1-a)*ln( sum_i exp( s_i(t-1)*Tn[i][j] ) )
// s(0) = feats[b,0,:], out[b,t,:] = s(t).
//
// Hybrid mapping (R7 compute x R5 I/O):
//  - one THREAD per batch: all 6 channels + full 6x6 softmaxed transition
//    matrix in registers -> zero shfl, huge in-thread ILP, MUFU is the only
//    loaded pipe (42 MUFU lane-ops per batch-step, the algorithmic floor).
//  - I/O staged through smem tiles [64 batches][16 steps * 6] with pitch 97
//    (odd -> conflict-free scalar LDS/STS; copy rounds warp-uniform,
//    global side fully coalesced via 192 = 3*64 constant-offset rounds).
//  - T split into NCHUNK=8 chunks of 128 (contraction ~0.2/step; W=12
//    warmup -> seed error ~5e-9). Fused store(k)+load(k+1) phase, all
//    compile-time bounds, 2 barriers per tile.

constexpr int T_STEPS  = 1024;
constexpr int C        = 6;
constexpr int BLOCK    = 64;            // threads = batches per block
constexpr int TT       = 16;            // steps per tile
constexpr int NTILE    = 8;             // tiles per chunk
constexpr int CT       = TT * NTILE;    // 128 steps per chunk
constexpr int NCHUNK   = T_STEPS / CT;  // 8
constexpr int W        = 12;            // warmup steps (incl. seed)
constexpr int ROW      = T_STEPS * C;   // 6144
constexpr int TILEF    = TT * C;        // 96 floats per (batch, tile)
constexpr int PITCH    = TILEF + 1;     // 97, odd -> conflict-free
constexpr float LOG2E_F = 1.4426950408889634f;
constexpr float LN2_F   = 0.6931471805599453f;

__device__ __forceinline__ float ex2f(float x) {
    float r; asm("ex2.approx.ftz.f32 %0, %1;" : "=f"(r) : "f"(x)); return r;
}
__device__ __forceinline__ float lg2f(float x) {
    float r; asm("lg2.approx.ftz.f32 %0, %1;" : "=f"(r) : "f"(x)); return r;
}

// One step, all 6 channels in-thread. t2[i*6+j] = Tn_softmax[i][j]*log2(e).
__device__ __forceinline__ void step6(float s[6], const float c[6],
                                      const float t2[36], float a, float c2) {
    float acc[6];
    #pragma unroll
    for (int j = 0; j < 6; ++j) {
        float e0 = ex2f(s[0] * t2[0 * 6 + j]);
        float e1 = ex2f(s[1] * t2[1 * 6 + j]);
        float e2 = ex2f(s[2] * t2[2 * 6 + j]);
        float e3 = ex2f(s[3] * t2[3 * 6 + j]);
        float e4 = ex2f(s[4] * t2[4 * 6 + j]);
        float e5 = ex2f(s[5] * t2[5 * 6 + j]);
        acc[j] = ((e0 + e1) + (e2 + e3)) + (e4 + e5);
    }
    #pragma unroll
    for (int j = 0; j < 6; ++j)
        s[j] = fmaf(a, c[j], c2 * lg2f(acc[j]));
}

__device__ __forceinline__ void load12(const float* p, float c[12]) {
    float4 v0 = *reinterpret_cast<const float4*>(p);
    float4 v1 = *reinterpret_cast<const float4*>(p + 4);
    float4 v2 = *reinterpret_cast<const float4*>(p + 8);
    c[0]=v0.x; c[1]=v0.y; c[2]=v0.z;  c[3]=v0.w;
    c[4]=v1.x; c[5]=v1.y; c[6]=v1.z;  c[7]=v1.w;
    c[8]=v2.x; c[9]=v2.y; c[10]=v2.z; c[11]=v2.w;
}

__global__ __launch_bounds__(BLOCK, 8)
void transfer_kernel(const float* __restrict__ feats,
                     const float* __restrict__ alpha,
                     const float* __restrict__ trans,
                     float* __restrict__ out, int B)
{
    __shared__ float sm[BLOCK * PITCH];   // 24832 B

    const int tid = threadIdx.x;
    const int b0  = blockIdx.x * BLOCK;
    const int chunk = blockIdx.y;
    const int t0 = chunk * CT;
    int nvalid = B - b0; if (nvalid > BLOCK) nvalid = BLOCK;

    // a = sigmoid(alpha)
    const float av = alpha[0];
    const float a  = 1.0f / (1.0f + __expf(-av));
    const float c2 = (1.0f - a) * LN2_F;

    // Full row-softmax of transitions, scaled by log2(e). 36 regs.
    float t2[36];
    #pragma unroll
    for (int i = 0; i < 6; ++i) {
        float row[6], m = -1e30f;
        #pragma unroll
        for (int k = 0; k < 6; ++k) { row[k] = trans[i * 6 + k]; m = fmaxf(m, row[k]); }
        float sum = 0.f;
        #pragma unroll
        for (int k = 0; k < 6; ++k) { row[k] = ex2f((row[k] - m) * LOG2E_F); sum += row[k]; }
        float inv = LOG2E_F / sum;
        #pragma unroll
        for (int k = 0; k < 6; ++k) t2[i * 6 + k] = row[k] * inv;
    }

    // Copy-round constant offsets: per pair of batches, 192 = 3*64 floats.
    //  round0: r=tid        -> batch 0 of pair, idx tid
    //  round1: r=tid+64     -> tid<32: batch0 idx tid+64 ; else batch1 idx tid-32
    //  round2: r=tid+128    -> batch1, idx tid+32
    // Branch is warp-uniform (warp0: tid<32, warp1: tid>=32).
    const bool loh = (tid < 32);
    const int  s1  = loh ? (64 + tid) : (PITCH + tid - 32);
    const int  g1  = loh ? (64 + tid) : (ROW + tid - 32);
    const int  s2  = PITCH + 32 + tid;
    const long g2  = (long)ROW + 32 + tid;

    const bool full = (nvalid == BLOCK);

    const float* fbase = feats + (size_t)b0 * ROW + (size_t)t0 * C;
    float*       obase = out   + (size_t)b0 * ROW + (size_t)t0 * C;

    float s[6];

    // ---- warmup (chunks > 0): seed s = feats[t0-W], 11 unstored steps ----
    if (chunk > 0) {
        int bb = b0 + tid; if (bb >= B) bb = B - 1;
        const float* wp = feats + (size_t)bb * ROW + (size_t)(t0 - W) * C;
        float cw[12];
        load12(wp, cw);
        #pragma unroll
        for (int j = 0; j < 6; ++j) s[j] = cw[j];
        step6(s, cw + 6, t2, a, c2);
        #pragma unroll
        for (int k = 1; k < W / 2; ++k) {
            load12(wp + k * 12, cw);
            step6(s, cw,     t2, a, c2);
            step6(s, cw + 6, t2, a, c2);
        }
    }

    // ---- initial load: tile 0 ----
    if (full) {
        #pragma unroll
        for (int p = 0; p < BLOCK / 2; ++p) {
            const float* g0 = fbase + (size_t)(2 * p) * ROW;
            float* sp = sm + 2 * p * PITCH;
            sp[tid] = g0[tid];
            sp[s1]  = g0[g1];
            sp[s2]  = g0[g2];
        }
    } else {
        #pragma unroll 1
        for (int p = 0; p < BLOCK / 2; ++p) {
            int bl = 2 * p;
            const float* g0 = fbase + (size_t)bl * ROW;
            float* sp = sm + bl * PITCH;
            if (bl + 1 < nvalid) { sp[tid] = g0[tid]; sp[s1] = g0[g1]; sp[s2] = g0[g2]; }
            else if (bl < nvalid) { sp[tid] = g0[tid]; if (loh) sp[s1] = g0[g1]; }
        }
    }

    float* srow = sm + tid * PITCH;
    const bool own = (b0 + tid < B);

    #pragma unroll 1
    for (int k = 0; k < NTILE; ++k) {
        __syncthreads();

        // ---- compute tile k in place (thread = batch, scalar LDS/STS) ----
        if (own) {
            int tstart = 0;
            if (chunk == 0 && k == 0) {
                #pragma unroll
                for (int j = 0; j < 6; ++j) s[j] = srow[j];
                tstart = 1;   // slot 0 already holds s(0)
            }
            #pragma unroll 4
            for (int tt = tstart; tt < TT; ++tt) {
                float c[6];
                #pragma unroll
                for (int j = 0; j < 6; ++j) c[j] = srow[tt * 6 + j];
                step6(s, c, t2, a, c2);
                #pragma unroll
                for (int j = 0; j < 6; ++j) srow[tt * 6 + j] = s[j];
            }
        }
        __syncthreads();

        // ---- fused: store tile k (LDS->STG) + load tile k+1 (LDG->STS).
        //      Same thread owns both accesses to each smem word: program
        //      order guarantees the read-before-write. ----
        float* gd = obase + (size_t)(k * TILEF);
        const float* gl = fbase + (size_t)((k + 1) * TILEF);
        const bool more = (k + 1 < NTILE);

        if (full) {
            #pragma unroll
            for (int p = 0; p < BLOCK / 2; ++p) {
                float* g0 = gd + (size_t)(2 * p) * ROW;
                float* sp = sm + 2 * p * PITCH;
                g0[tid] = sp[tid];
                g0[g1]  = sp[s1];
                g0[g2]  = sp[s2];
                if (more) {
                    const float* gi = gl + (size_t)(2 * p) * ROW;
                    sp[tid] = gi[tid];
                    sp[s1]  = gi[g1];
                    sp[s2]  = gi[g2];
                }
            }
        } else {
            #pragma unroll 1
            for (int p = 0; p < BLOCK / 2; ++p) {
                int bl = 2 * p;
                float* g0 = gd + (size_t)bl * ROW;
                float* sp = sm + bl * PITCH;
                if (bl + 1 < nvalid) {
                    g0[tid] = sp[tid]; g0[g1] = sp[s1]; g0[g2] = sp[s2];
                    if (more) {
                        const float* gi = gl + (size_t)bl * ROW;
                        sp[tid] = gi[tid]; sp[s1] = gi[g1]; sp[s2] = gi[g2];
                    }
                } else if (bl < nvalid) {
                    g0[tid] = sp[tid]; if (loh) g0[g1] = sp[s1];
                    if (more) {
                        const float* gi = gl + (size_t)bl * ROW;
                        sp[tid] = gi[tid]; if (loh) sp[s1] = gi[g1];
                    }
                }
            }
        }
    }
}

extern "C" void kernel_launch(void* const* d_in, const int* in_sizes, int n_in,
                              void* d_out, int out_size) {
    const float* feats = (const float*)d_in[0];
    const float* alpha = (const float*)d_in[1];
    const float* trans = (const float*)d_in[2];
    float* out = (float*)d_out;
    (void)n_in; (void)out_size;

    int B = in_sizes[0] / (T_STEPS * C);
    dim3 grid((B + BLOCK - 1) / BLOCK, NCHUNK);
    transfer_kernel<<<grid, BLOCK>>>(feats, alpha, trans, out, B);
}